// round 13
// baseline (speedup 1.0000x reference)
#include <cuda_runtime.h>

// Problem constants
#define BB    64
#define CC    128
#define TT    500
#define NRES  2048
#define NCLS  10
#define DECAY 0.9f
#define VTH   1.0f

// Eigen gebp single-thread kc (CONFIRMED bit-exact). Do not change.
#define KCHUNK 232

#define NRES_BLOCKS 128     // 16 neurons per reservoir block
#define CLF_BLOCKS  2
#define THREADS 512
#define JPAD 20             // smem row stride in floats for 16-j W rows

#define SMEM_BYTES (NRES * JPAD * 4 + 64 * 4)   // W tile + 64 mask words

// Persistent device scratch
__device__ float    g_FF[(size_t)TT * BB * NRES]; // precomputed feedforward
__device__ float    g_vr[BB * NRES];
__device__ float    g_vc[BB * NCLS];
// Segmented spike lists: per (buf, b, slice) up to 16 ascending k's + count.
__device__ unsigned short g_slist[2][BB][NRES_BLOCKS][16];
__device__ unsigned char  g_scnt[2][BB * NRES_BLOCKS];
__device__ float    g_WinT[CC * NRES];            // W_in transposed [c][j]
__device__ float    g_Wslice[(size_t)NRES_BLOCKS * NRES * 16]; // [slice][k][jl]

// ---------------------------------------------------------------------------
__global__ void zero_init_kernel(float* d_out, int out_size) {
    int i = blockIdx.x * blockDim.x + threadIdx.x;
    if (i < BB * NRES)                  g_vr[i] = 0.0f;
    if (i < BB * NCLS)                  g_vc[i] = 0.0f;
    if (i < 2 * BB * NRES_BLOCKS)       (&g_scnt[0][0])[i] = 0;
    if (i < out_size)                   d_out[i] = 0.0f;
}

// ---------------------------------------------------------------------------
__global__ void transpose_win_kernel(const float* __restrict__ Win) {
    int i = blockIdx.x * blockDim.x + threadIdx.x;
    if (i < CC * NRES) {
        int c = i / NRES;
        int j = i % NRES;
        g_WinT[i] = Win[j * CC + c];
    }
}

// ---------------------------------------------------------------------------
// g_Wslice[j>>4][k][j&15] = Wres[j][k], tiled 32x32 transpose.
__global__ void build_wslice_kernel(const float* __restrict__ Wres) {
    __shared__ float tile[32][33];
    int kBase = blockIdx.x * 32;
    int jBase = blockIdx.y * 32;
    int tx = threadIdx.x;
    int ty = threadIdx.y;
    for (int r = ty; r < 32; r += 8)
        tile[r][tx] = Wres[(size_t)(jBase + r) * NRES + kBase + tx];
    __syncthreads();
    for (int r = ty; r < 32; r += 8) {
        int k = kBase + r;
        int j = jBase + tx;
        g_Wslice[((size_t)(j >> 4) * NRES + k) * 16 + (j & 15)] = tile[tx][r];
    }
}

// ---------------------------------------------------------------------------
// FF[t][b][j]: strict serial ascending-c fp32 FMA (frozen contract).
__global__ void __launch_bounds__(256) ff_kernel(const float* __restrict__ x) {
    int t = blockIdx.x / BB;
    int b = blockIdx.x % BB;
    __shared__ float xs[CC];
    int tid = threadIdx.x;
    if (tid < CC) xs[tid] = x[(size_t)b * CC * TT + tid * TT + t];
    __syncthreads();

    const float4* W4 = (const float4*)g_WinT;
    float a0 = 0.f, a1 = 0.f, a2 = 0.f, a3 = 0.f;
    float a4 = 0.f, a5 = 0.f, a6 = 0.f, a7 = 0.f;
    #pragma unroll 4
    for (int c = 0; c < CC; c++) {
        float xv = xs[c];
        float4 w0 = W4[c * (NRES / 4) + tid];
        float4 w1 = W4[c * (NRES / 4) + tid + 256];
        a0 = fmaf(xv, w0.x, a0); a1 = fmaf(xv, w0.y, a1);
        a2 = fmaf(xv, w0.z, a2); a3 = fmaf(xv, w0.w, a3);
        a4 = fmaf(xv, w1.x, a4); a5 = fmaf(xv, w1.y, a5);
        a6 = fmaf(xv, w1.z, a6); a7 = fmaf(xv, w1.w, a7);
    }
    float4* out = (float4*)(g_FF + (size_t)t * BB * NRES + (size_t)b * NRES);
    out[tid]       = make_float4(a0, a1, a2, a3);
    out[tid + 256] = make_float4(a4, a5, a6, a7);
}

// ---------------------------------------------------------------------------
// Sparse step over SEGMENTED spike lists (no extra compaction launch).
// Consumer walks slices 0..127 in order; entries within a slice are
// ascending -> global ascending k, identical flush sequence: BIT-EXACT
// vs the confirmed chain (FADD == fmaf(1,w,p); skips == fmaf(0,w,p)).
__global__ void __launch_bounds__(THREADS, 1)
step_kernel(int step,
            const float* __restrict__ Wclf,
            float* __restrict__ d_out) {
    extern __shared__ float sm[];
    unsigned* msk = (unsigned*)(sm + NRES * JPAD);
    int tid = threadIdx.x;
    int bid = blockIdx.x;
    int rb = (step + 1) & 1;
    int wb = step & 1;

    if (bid < NRES_BLOCKS) {
        if (step >= TT) return;
        if (tid < 64) msk[tid] = 0u;

        // Stage W slice [2048 k][16 j] -> smem [k][JPAD].
        {
            const float4* src = (const float4*)(g_Wslice + (size_t)bid * NRES * 16);
            float4* dst = (float4*)sm;
            #pragma unroll
            for (int u = 0; u < 16; u++) {
                int f = tid + u * THREADS;   // 0..8191
                int k = f >> 2, q = f & 3;
                dst[k * (JPAD / 4) + q] = src[f];
            }
        }

        int b  = tid >> 3;          // 0..63
        int jp = tid & 7;           // 0..7 (j-pair)
        size_t off = (size_t)b * NRES + bid * 16 + jp * 2;
        float2 ff = *(const float2*)(g_FF + (size_t)step * BB * NRES + off);
        float2 v  = *(const float2*)(g_vr + off);
        const unsigned char*  cnt = &g_scnt[rb][b * NRES_BLOCKS];
        const unsigned short (*seg)[16] = g_slist[rb][b];
        __syncthreads();

        float acc0 = 0.f, acc1 = 0.f, p0 = 0.f, p1 = 0.f;
        int nextb = KCHUNK;
        for (int i = 0; i < NRES_BLOCKS; i++) {
            int c = cnt[i];
            for (int e = 0; e < c; e++) {
                int k = seg[i][e];
                while (k >= nextb) {  // crossed chunk boundary: exact flush
                    acc0 = __fadd_rn(acc0, p0); p0 = 0.f;
                    acc1 = __fadd_rn(acc1, p1); p1 = 0.f;
                    nextb += KCHUNK;
                }
                float2 w = *(const float2*)&sm[k * JPAD + jp * 2];
                p0 = __fadd_rn(p0, w.x);
                p1 = __fadd_rn(p1, w.y);
            }
        }
        acc0 = __fadd_rn(acc0, p0);
        acc1 = __fadd_rn(acc1, p1);

        // Epilogue: I = ff + rec (single RN add), v = 0.9*v + I UNCONTRACTED.
        float I0 = __fadd_rn(ff.x, acc0);
        float I1 = __fadd_rn(ff.y, acc1);
        v.x = __fadd_rn(__fmul_rn(DECAY, v.x), I0);
        v.y = __fadd_rn(__fmul_rn(DECAY, v.y), I1);
        unsigned b0 = (v.x >= VTH) ? 1u : 0u;
        unsigned b1 = (v.y >= VTH) ? 1u : 0u;
        if (b0) v.x = 0.0f;
        if (b1) v.y = 0.0f;
        *(float2*)(g_vr + off) = v;

        float2* ac = (float2*)(d_out + NCLS * BB + off);
        float2 a = *ac;
        a.x += (float)b0; a.y += (float)b1;
        *ac = a;

        // Publish spike bits, then emit this slice's segment (ascending).
        unsigned nib = b0 | (b1 << 1);
        atomicOr(&msk[b], nib << (jp * 2));
        __syncthreads();
        if (tid < 64) {
            unsigned m = msk[tid];      // 16 valid bits
            unsigned short* dst = &g_slist[wb][tid][bid][0];
            int pos = 0;
            while (m) {
                unsigned t = m & (0u - m);
                dst[pos++] = (unsigned short)(bid * 16 + __popc(t - 1u));
                m ^= t;
            }
            g_scnt[wb][tid * NRES_BLOCKS + bid] = (unsigned char)pos;
        }
    } else {
        // Classifier for s_{step-1}: serial ascending-k adds over segments
        // (bit-identical to the confirmed serial chain).
        if (step == 0) return;
        int idx = (bid - NRES_BLOCKS) * THREADS + tid;
        if (idx >= BB * NCLS) return;
        int b   = idx / NCLS;
        int cls = idx % NCLS;
        const unsigned char*  cnt = &g_scnt[rb][b * NRES_BLOCKS];
        const unsigned short (*seg)[16] = g_slist[rb][b];
        const float* wr = Wclf + (size_t)cls * NRES;
        float acc = 0.f;
        for (int i = 0; i < NRES_BLOCKS; i++) {
            int c = cnt[i];
            for (int e = 0; e < c; e++)
                acc = __fadd_rn(acc, wr[seg[i][e]]);
        }
        float vc = g_vc[idx];
        vc = __fadd_rn(__fmul_rn(DECAY, vc), acc);
        if (vc >= VTH) {
            d_out[idx] += 1.0f;
            vc = 0.0f;
        }
        g_vc[idx] = vc;
    }
}

// ---------------------------------------------------------------------------
extern "C" void kernel_launch(void* const* d_in, const int* in_sizes, int n_in,
                              void* d_out, int out_size) {
    const float* x    = (const float*)d_in[0];  // (64,128,500)
    const float* Win  = (const float*)d_in[1];  // (2048,128)
    const float* Wres = (const float*)d_in[2];  // (2048,2048)
    const float* Wclf = (const float*)d_in[3];  // (10,2048)
    float* out = (float*)d_out;                 // [640 counts | 131072 accum]

    cudaFuncSetAttribute(step_kernel,
                         cudaFuncAttributeMaxDynamicSharedMemorySize, SMEM_BYTES);

    {
        int n = BB * NRES;
        if (out_size > n) n = out_size;
        int grid = (n + 255) / 256;
        zero_init_kernel<<<grid, 256>>>(out, out_size);
    }

    transpose_win_kernel<<<(CC * NRES + 255) / 256, 256>>>(Win);
    build_wslice_kernel<<<dim3(NRES / 32, NRES / 32), dim3(32, 8)>>>(Wres);

    // Precompute all feedforward drives FF[t][b][j]
    ff_kernel<<<TT * BB, 256>>>(x);

    // Sequential LIF steps; step==TT runs only the final classifier.
    for (int t = 0; t <= TT; t++) {
        step_kernel<<<NRES_BLOCKS + CLF_BLOCKS, THREADS, SMEM_BYTES>>>(
            t, Wclf, out);
    }
}

// round 14
// speedup vs baseline: 1.4592x; 1.4592x over previous
#include <cuda_runtime.h>

// Problem constants
#define BB    64
#define CC    128
#define TT    500
#define NRES  2048
#define NCLS  10
#define DECAY 0.9f
#define VTH   1.0f

// Eigen gebp single-thread kc (CONFIRMED bit-exact). Do not change.
#define KCHUNK 232

#define NRES_BLOCKS 128     // 16 neurons per reservoir block
#define CLF_BLOCKS  2
#define THREADS 512
#define JPAD 20             // smem row stride in floats for 16-j W rows
#define LSTRIDE 260         // u16 stride per-b chunk list (bank-skewed)

#define SMEM_BYTES (NRES * JPAD * 4 + 64 * 4 + 64 * LSTRIDE * 2)

// Persistent device scratch
__device__ float    g_FF[(size_t)TT * BB * NRES]; // precomputed feedforward
__device__ float    g_vr[BB * NRES];
__device__ float    g_vc[BB * NCLS];
__device__ unsigned g_mask[2][BB * NRES_BLOCKS];  // 16 spike bits per (b,slice)
__device__ float    g_WinT[CC * NRES];            // W_in transposed [c][j]
__device__ float    g_Wslice[(size_t)NRES_BLOCKS * NRES * 16]; // [slice][k][jl]

// ---------------------------------------------------------------------------
__global__ void zero_init_kernel(float* d_out, int out_size) {
    int i = blockIdx.x * blockDim.x + threadIdx.x;
    if (i < BB * NRES)                  g_vr[i] = 0.0f;
    if (i < BB * NCLS)                  g_vc[i] = 0.0f;
    if (i < 2 * BB * NRES_BLOCKS)       (&g_mask[0][0])[i] = 0u;
    if (i < out_size)                   d_out[i] = 0.0f;
}

// ---------------------------------------------------------------------------
__global__ void transpose_win_kernel(const float* __restrict__ Win) {
    int i = blockIdx.x * blockDim.x + threadIdx.x;
    if (i < CC * NRES) {
        int c = i / NRES;
        int j = i % NRES;
        g_WinT[i] = Win[j * CC + c];
    }
}

// ---------------------------------------------------------------------------
// g_Wslice[j>>4][k][j&15] = Wres[j][k], tiled 32x32 transpose.
__global__ void build_wslice_kernel(const float* __restrict__ Wres) {
    __shared__ float tile[32][33];
    int kBase = blockIdx.x * 32;
    int jBase = blockIdx.y * 32;
    int tx = threadIdx.x;
    int ty = threadIdx.y;
    for (int r = ty; r < 32; r += 8)
        tile[r][tx] = Wres[(size_t)(jBase + r) * NRES + kBase + tx];
    __syncthreads();
    for (int r = ty; r < 32; r += 8) {
        int k = kBase + r;
        int j = jBase + tx;
        g_Wslice[((size_t)(j >> 4) * NRES + k) * 16 + (j & 15)] = tile[tx][r];
    }
}

// ---------------------------------------------------------------------------
// FF[t][b][j]: strict serial ascending-c fp32 FMA (frozen contract).
__global__ void __launch_bounds__(256) ff_kernel(const float* __restrict__ x) {
    int t = blockIdx.x / BB;
    int b = blockIdx.x % BB;
    __shared__ float xs[CC];
    int tid = threadIdx.x;
    if (tid < CC) xs[tid] = x[(size_t)b * CC * TT + tid * TT + t];
    __syncthreads();

    const float4* W4 = (const float4*)g_WinT;
    float a0 = 0.f, a1 = 0.f, a2 = 0.f, a3 = 0.f;
    float a4 = 0.f, a5 = 0.f, a6 = 0.f, a7 = 0.f;
    #pragma unroll 4
    for (int c = 0; c < CC; c++) {
        float xv = xs[c];
        float4 w0 = W4[c * (NRES / 4) + tid];
        float4 w1 = W4[c * (NRES / 4) + tid + 256];
        a0 = fmaf(xv, w0.x, a0); a1 = fmaf(xv, w0.y, a1);
        a2 = fmaf(xv, w0.z, a2); a3 = fmaf(xv, w0.w, a3);
        a4 = fmaf(xv, w1.x, a4); a5 = fmaf(xv, w1.y, a5);
        a6 = fmaf(xv, w1.z, a6); a7 = fmaf(xv, w1.w, a7);
    }
    float4* out = (float4*)(g_FF + (size_t)t * BB * NRES + (size_t)b * NRES);
    out[tid]       = make_float4(a0, a1, a2, a3);
    out[tid + 256] = make_float4(a4, a5, a6, a7);
}

// ---------------------------------------------------------------------------
// Sparse step: per 256-k chunk, the 8 threads of each b decode that b's mask
// words into an ascending smem k-list (warp prefix scan), then all 8 consume
// it with a 4-wide batched fast path. Same k sequence, same 232-boundary
// flushes, same __fadd_rn order => BIT-EXACT vs the confirmed chain.
__global__ void __launch_bounds__(THREADS, 1)
step_kernel(int step,
            const float* __restrict__ Wclf,
            float* __restrict__ d_out) {
    extern __shared__ float sm[];
    unsigned* msk = (unsigned*)(sm + NRES * JPAD);
    unsigned short* list = (unsigned short*)(msk + 64);
    int tid = threadIdx.x;
    int bid = blockIdx.x;
    int rb = (step + 1) & 1;
    int wb = step & 1;

    if (bid < NRES_BLOCKS) {
        if (step >= TT) return;
        if (tid < 64) msk[tid] = 0u;

        // Stage W slice [2048 k][16 j] -> smem [k][JPAD].
        {
            const float4* src = (const float4*)(g_Wslice + (size_t)bid * NRES * 16);
            float4* dst = (float4*)sm;
            #pragma unroll
            for (int u = 0; u < 16; u++) {
                int f = tid + u * THREADS;   // 0..8191
                int k = f >> 2, q = f & 3;
                dst[k * (JPAD / 4) + q] = src[f];
            }
        }

        int b    = tid >> 3;         // 0..63
        int jp   = tid & 7;          // 0..7
        int lane = tid & 31;
        size_t off = (size_t)b * NRES + bid * 16 + jp * 2;
        float2 ff = *(const float2*)(g_FF + (size_t)step * BB * NRES + off);
        float2 v  = *(const float2*)(g_vr + off);
        const unsigned* mrow = &g_mask[rb][b * NRES_BLOCKS];
        unsigned short* lb = list + b * LSTRIDE;
        __syncthreads();

        float acc0 = 0.f, acc1 = 0.f, p0 = 0.f, p1 = 0.f;
        int nextb = KCHUNK;

        for (int ch = 0; ch < 8; ch++) {     // 8 chunks of 256 k
            // Decode: this thread owns 2 mask words of chunk ch.
            unsigned w0 = mrow[ch * 16 + jp * 2];
            unsigned w1 = mrow[ch * 16 + jp * 2 + 1];
            int c = __popc(w0) + __popc(w1);
            int incl = c;
            #pragma unroll
            for (int d = 1; d < 8; d <<= 1) {
                int n = __shfl_up_sync(0xFFFFFFFFu, incl, d);
                if ((lane & 7) >= d) incl += n;
            }
            int pos = incl - c;                       // exclusive offset
            int tot = __shfl_sync(0xFFFFFFFFu, incl, lane | 7);
            int kb = ch * 256 + jp * 32;
            unsigned m = w0;
            while (m) {
                unsigned t = m & (0u - m);
                lb[pos++] = (unsigned short)(kb + __popc(t - 1u));
                m ^= t;
            }
            m = w1; kb += 16;
            while (m) {
                unsigned t = m & (0u - m);
                lb[pos++] = (unsigned short)(kb + __popc(t - 1u));
                m ^= t;
            }
            __syncwarp();

            // Consume: 4-wide batched (loads reordered, adds in order).
            int e = 0;
            for (; e + 4 <= tot; e += 4) {
                int k0 = lb[e],     k1 = lb[e + 1];
                int k2 = lb[e + 2], k3 = lb[e + 3];
                if (k3 < nextb) {                     // no boundary in batch
                    float2 a = *(const float2*)&sm[k0 * JPAD + jp * 2];
                    float2 bq = *(const float2*)&sm[k1 * JPAD + jp * 2];
                    float2 cq = *(const float2*)&sm[k2 * JPAD + jp * 2];
                    float2 dq = *(const float2*)&sm[k3 * JPAD + jp * 2];
                    p0 = __fadd_rn(p0, a.x);  p1 = __fadd_rn(p1, a.y);
                    p0 = __fadd_rn(p0, bq.x); p1 = __fadd_rn(p1, bq.y);
                    p0 = __fadd_rn(p0, cq.x); p1 = __fadd_rn(p1, cq.y);
                    p0 = __fadd_rn(p0, dq.x); p1 = __fadd_rn(p1, dq.y);
                } else {                              // boundary: exact path
                    #pragma unroll
                    for (int q = 0; q < 4; q++) {
                        int k = lb[e + q];
                        while (k >= nextb) {
                            acc0 = __fadd_rn(acc0, p0); p0 = 0.f;
                            acc1 = __fadd_rn(acc1, p1); p1 = 0.f;
                            nextb += KCHUNK;
                        }
                        float2 w = *(const float2*)&sm[k * JPAD + jp * 2];
                        p0 = __fadd_rn(p0, w.x);
                        p1 = __fadd_rn(p1, w.y);
                    }
                }
            }
            for (; e < tot; e++) {
                int k = lb[e];
                while (k >= nextb) {
                    acc0 = __fadd_rn(acc0, p0); p0 = 0.f;
                    acc1 = __fadd_rn(acc1, p1); p1 = 0.f;
                    nextb += KCHUNK;
                }
                float2 w = *(const float2*)&sm[k * JPAD + jp * 2];
                p0 = __fadd_rn(p0, w.x);
                p1 = __fadd_rn(p1, w.y);
            }
            __syncwarp();
        }
        acc0 = __fadd_rn(acc0, p0);
        acc1 = __fadd_rn(acc1, p1);

        // Epilogue: I = ff + rec (single RN add), v = 0.9*v + I UNCONTRACTED.
        float I0 = __fadd_rn(ff.x, acc0);
        float I1 = __fadd_rn(ff.y, acc1);
        v.x = __fadd_rn(__fmul_rn(DECAY, v.x), I0);
        v.y = __fadd_rn(__fmul_rn(DECAY, v.y), I1);
        unsigned b0 = (v.x >= VTH) ? 1u : 0u;
        unsigned b1 = (v.y >= VTH) ? 1u : 0u;
        if (b0) v.x = 0.0f;
        if (b1) v.y = 0.0f;
        *(float2*)(g_vr + off) = v;

        float2* ac = (float2*)(d_out + NCLS * BB + off);
        float2 a = *ac;
        a.x += (float)b0; a.y += (float)b1;
        *ac = a;

        unsigned nib = b0 | (b1 << 1);
        atomicOr(&msk[b], nib << (jp * 2));
        __syncthreads();
        if (tid < 64) g_mask[wb][tid * NRES_BLOCKS + bid] = msk[tid];
    } else {
        // Classifier for s_{step-1}: serial ascending-k adds via mask walk
        // (bit-identical to the confirmed serial chain).
        if (step == 0) return;
        int idx = (bid - NRES_BLOCKS) * THREADS + tid;
        if (idx >= BB * NCLS) return;
        int b   = idx / NCLS;
        int cls = idx % NCLS;
        const unsigned* mrow = &g_mask[rb][b * NRES_BLOCKS];
        const float* wr = Wclf + (size_t)cls * NRES;
        float acc = 0.f;
        for (int i = 0; i < NRES_BLOCKS; i++) {
            unsigned m = mrow[i];
            while (m) {
                unsigned t = m & (0u - m);
                int k = (i << 4) + __popc(t - 1u);
                m ^= t;
                acc = __fadd_rn(acc, wr[k]);
            }
        }
        float vc = g_vc[idx];
        vc = __fadd_rn(__fmul_rn(DECAY, vc), acc);
        if (vc >= VTH) {
            d_out[idx] += 1.0f;
            vc = 0.0f;
        }
        g_vc[idx] = vc;
    }
}

// ---------------------------------------------------------------------------
extern "C" void kernel_launch(void* const* d_in, const int* in_sizes, int n_in,
                              void* d_out, int out_size) {
    const float* x    = (const float*)d_in[0];  // (64,128,500)
    const float* Win  = (const float*)d_in[1];  // (2048,128)
    const float* Wres = (const float*)d_in[2];  // (2048,2048)
    const float* Wclf = (const float*)d_in[3];  // (10,2048)
    float* out = (float*)d_out;                 // [640 counts | 131072 accum]

    cudaFuncSetAttribute(step_kernel,
                         cudaFuncAttributeMaxDynamicSharedMemorySize, SMEM_BYTES);

    {
        int n = BB * NRES;
        if (out_size > n) n = out_size;
        int grid = (n + 255) / 256;
        zero_init_kernel<<<grid, 256>>>(out, out_size);
    }

    transpose_win_kernel<<<(CC * NRES + 255) / 256, 256>>>(Win);
    build_wslice_kernel<<<dim3(NRES / 32, NRES / 32), dim3(32, 8)>>>(Wres);

    // Precompute all feedforward drives FF[t][b][j]
    ff_kernel<<<TT * BB, 256>>>(x);

    // Sequential LIF steps; step==TT runs only the final classifier.
    for (int t = 0; t <= TT; t++) {
        step_kernel<<<NRES_BLOCKS + CLF_BLOCKS, THREADS, SMEM_BYTES>>>(
            t, Wclf, out);
    }
}

// round 15
// speedup vs baseline: 1.4604x; 1.0008x over previous
#include <cuda_runtime.h>

// Problem constants
#define BB    64
#define CC    128
#define TT    500
#define NRES  2048
#define NCLS  10
#define DECAY 0.9f
#define VTH   1.0f

// Eigen gebp single-thread kc (CONFIRMED bit-exact). Do not change.
#define KCHUNK 232

#define NRES_BLOCKS 128     // 16 neurons per reservoir block
#define CLF_BLOCKS  2
#define GRID_BLOCKS (NRES_BLOCKS + CLF_BLOCKS)   // 130 <= 148 SMs, 1 blk/SM
#define THREADS 512
#define JPAD 20             // smem row stride in floats for 16-j W rows
#define LSTRIDE 260         // u16 stride per-b chunk list

#define SMEM_BYTES (NRES * JPAD * 4 + 64 * 4 + 64 * LSTRIDE * 2)

// Persistent device scratch
__device__ float    g_FF[(size_t)TT * BB * NRES]; // precomputed feedforward
__device__ unsigned g_mask[2][BB * NRES_BLOCKS];  // 16 spike bits per (b,slice)
__device__ float    g_WinT[CC * NRES];            // W_in transposed [c][j]
__device__ float    g_Wslice[(size_t)NRES_BLOCKS * NRES * 16]; // [slice][k][jl]
__device__ unsigned g_bar_count;
__device__ unsigned g_bar_sense;

// ---------------------------------------------------------------------------
__global__ void zero_init_kernel() {
    int i = blockIdx.x * blockDim.x + threadIdx.x;
    // s_{-1} = 0: zero the buffer read at t=0 (rb=1). Zero both for safety.
    if (i < 2 * BB * NRES_BLOCKS) (&g_mask[0][0])[i] = 0u;
    if (i == 0) { g_bar_count = 0u; g_bar_sense = 0u; }
}

// ---------------------------------------------------------------------------
__global__ void transpose_win_kernel(const float* __restrict__ Win) {
    int i = blockIdx.x * blockDim.x + threadIdx.x;
    if (i < CC * NRES) {
        int c = i / NRES;
        int j = i % NRES;
        g_WinT[i] = Win[j * CC + c];
    }
}

// ---------------------------------------------------------------------------
// g_Wslice[j>>4][k][j&15] = Wres[j][k], tiled 32x32 transpose.
__global__ void build_wslice_kernel(const float* __restrict__ Wres) {
    __shared__ float tile[32][33];
    int kBase = blockIdx.x * 32;
    int jBase = blockIdx.y * 32;
    int tx = threadIdx.x;
    int ty = threadIdx.y;
    for (int r = ty; r < 32; r += 8)
        tile[r][tx] = Wres[(size_t)(jBase + r) * NRES + kBase + tx];
    __syncthreads();
    for (int r = ty; r < 32; r += 8) {
        int k = kBase + r;
        int j = jBase + tx;
        g_Wslice[((size_t)(j >> 4) * NRES + k) * 16 + (j & 15)] = tile[tx][r];
    }
}

// ---------------------------------------------------------------------------
// FF[t][b][j]: strict serial ascending-c fp32 FMA (frozen contract).
__global__ void __launch_bounds__(256) ff_kernel(const float* __restrict__ x) {
    int t = blockIdx.x / BB;
    int b = blockIdx.x % BB;
    __shared__ float xs[CC];
    int tid = threadIdx.x;
    if (tid < CC) xs[tid] = x[(size_t)b * CC * TT + tid * TT + t];
    __syncthreads();

    const float4* W4 = (const float4*)g_WinT;
    float a0 = 0.f, a1 = 0.f, a2 = 0.f, a3 = 0.f;
    float a4 = 0.f, a5 = 0.f, a6 = 0.f, a7 = 0.f;
    #pragma unroll 4
    for (int c = 0; c < CC; c++) {
        float xv = xs[c];
        float4 w0 = W4[c * (NRES / 4) + tid];
        float4 w1 = W4[c * (NRES / 4) + tid + 256];
        a0 = fmaf(xv, w0.x, a0); a1 = fmaf(xv, w0.y, a1);
        a2 = fmaf(xv, w0.z, a2); a3 = fmaf(xv, w0.w, a3);
        a4 = fmaf(xv, w1.x, a4); a5 = fmaf(xv, w1.y, a5);
        a6 = fmaf(xv, w1.z, a6); a7 = fmaf(xv, w1.w, a7);
    }
    float4* out = (float4*)(g_FF + (size_t)t * BB * NRES + (size_t)b * NRES);
    out[tid]       = make_float4(a0, a1, a2, a3);
    out[tid + 256] = make_float4(a4, a5, a6, a7);
}

// ---------------------------------------------------------------------------
// Sense-reversing grid barrier. All 130 blocks are co-resident (1 blk/SM by
// smem), so spinning is safe. Only thread 0 spins; rest wait at bar.sync.
__device__ __forceinline__ void grid_barrier(unsigned* sense_sm) {
    __syncthreads();
    if (threadIdx.x == 0) {
        unsigned s = *sense_sm ^ 1u;
        *sense_sm = s;
        __threadfence();
        unsigned v = atomicAdd(&g_bar_count, 1u);
        if (v == GRID_BLOCKS - 1u) {
            atomicExch(&g_bar_count, 0u);
            __threadfence();
            atomicExch(&g_bar_sense, s);
        } else {
            volatile unsigned* vs = &g_bar_sense;
            while (*vs != s) __nanosleep(128);
        }
        __threadfence();
    }
    __syncthreads();
}

// ---------------------------------------------------------------------------
// PERSISTENT simulation kernel: all 501 steps in one launch.
// Blocks [0,128): reservoir (16 neurons each); blocks 128-129: classifier.
// W slice staged ONCE; v / spike-accum / vc / counts live in registers for
// the whole run. Consume = R14's decode+batch (bit-exact: same ascending-k
// sequence, same 232-boundary flushes, same __fadd_rn order).
__global__ void __launch_bounds__(THREADS, 1)
sim_kernel(const float* __restrict__ Wclf, float* __restrict__ d_out) {
    extern __shared__ float sm[];
    unsigned* msk = (unsigned*)(sm + NRES * JPAD);
    unsigned short* list = (unsigned short*)(msk + 64);
    __shared__ unsigned sense_sm;
    int tid = threadIdx.x;
    int bid = blockIdx.x;
    if (tid == 0) sense_sm = 0u;

    // ---- reservoir-thread persistent state ----
    int b    = tid >> 3;          // 0..63
    int jp   = tid & 7;           // 0..7
    int lane = tid & 31;
    float vx = 0.f, vy = 0.f;     // membrane
    float sx = 0.f, sy = 0.f;     // spike accum
    // ---- classifier-thread persistent state ----
    int cidx = (bid - NRES_BLOCKS) * THREADS + tid;  // valid if bid>=128
    float vc = 0.f, cnt = 0.f;

    if (bid < NRES_BLOCKS) {
        // Stage W slice [2048 k][16 j] -> smem [k][JPAD], ONCE.
        const float4* src = (const float4*)(g_Wslice + (size_t)bid * NRES * 16);
        float4* dst = (float4*)sm;
        #pragma unroll
        for (int u = 0; u < 16; u++) {
            int f = tid + u * THREADS;
            int k = f >> 2, q = f & 3;
            dst[k * (JPAD / 4) + q] = src[f];
        }
    }
    __syncthreads();

    for (int t = 0; t <= TT; t++) {
        int rb = (t + 1) & 1;
        int wb = t & 1;

        if (bid < NRES_BLOCKS) {
            if (t < TT) {
                if (tid < 64) msk[tid] = 0u;
                size_t off = (size_t)b * NRES + bid * 16 + jp * 2;
                float2 ff = *(const float2*)(g_FF + (size_t)t * BB * NRES + off);
                const unsigned* mrow = &g_mask[rb][b * NRES_BLOCKS];
                unsigned short* lb = list + b * LSTRIDE;
                __syncthreads();   // msk zero visible before atomicOr later

                float acc0 = 0.f, acc1 = 0.f, p0 = 0.f, p1 = 0.f;
                int nextb = KCHUNK;

                for (int ch = 0; ch < 8; ch++) {     // 8 chunks of 256 k
                    unsigned w0 = mrow[ch * 16 + jp * 2];
                    unsigned w1 = mrow[ch * 16 + jp * 2 + 1];
                    int c = __popc(w0) + __popc(w1);
                    int incl = c;
                    #pragma unroll
                    for (int d = 1; d < 8; d <<= 1) {
                        int n = __shfl_up_sync(0xFFFFFFFFu, incl, d);
                        if ((lane & 7) >= d) incl += n;
                    }
                    int pos = incl - c;
                    int tot = __shfl_sync(0xFFFFFFFFu, incl, lane | 7);
                    int kb = ch * 256 + jp * 32;
                    unsigned m = w0;
                    while (m) {
                        unsigned u = m & (0u - m);
                        lb[pos++] = (unsigned short)(kb + __popc(u - 1u));
                        m ^= u;
                    }
                    m = w1; kb += 16;
                    while (m) {
                        unsigned u = m & (0u - m);
                        lb[pos++] = (unsigned short)(kb + __popc(u - 1u));
                        m ^= u;
                    }
                    __syncwarp();

                    int e = 0;
                    for (; e + 4 <= tot; e += 4) {
                        int k0 = lb[e],     k1 = lb[e + 1];
                        int k2 = lb[e + 2], k3 = lb[e + 3];
                        if (k3 < nextb) {            // no boundary in batch
                            float2 a  = *(const float2*)&sm[k0 * JPAD + jp * 2];
                            float2 bq = *(const float2*)&sm[k1 * JPAD + jp * 2];
                            float2 cq = *(const float2*)&sm[k2 * JPAD + jp * 2];
                            float2 dq = *(const float2*)&sm[k3 * JPAD + jp * 2];
                            p0 = __fadd_rn(p0, a.x);  p1 = __fadd_rn(p1, a.y);
                            p0 = __fadd_rn(p0, bq.x); p1 = __fadd_rn(p1, bq.y);
                            p0 = __fadd_rn(p0, cq.x); p1 = __fadd_rn(p1, cq.y);
                            p0 = __fadd_rn(p0, dq.x); p1 = __fadd_rn(p1, dq.y);
                        } else {                     // boundary: exact path
                            #pragma unroll
                            for (int q = 0; q < 4; q++) {
                                int k = lb[e + q];
                                while (k >= nextb) {
                                    acc0 = __fadd_rn(acc0, p0); p0 = 0.f;
                                    acc1 = __fadd_rn(acc1, p1); p1 = 0.f;
                                    nextb += KCHUNK;
                                }
                                float2 w = *(const float2*)&sm[k * JPAD + jp * 2];
                                p0 = __fadd_rn(p0, w.x);
                                p1 = __fadd_rn(p1, w.y);
                            }
                        }
                    }
                    for (; e < tot; e++) {
                        int k = lb[e];
                        while (k >= nextb) {
                            acc0 = __fadd_rn(acc0, p0); p0 = 0.f;
                            acc1 = __fadd_rn(acc1, p1); p1 = 0.f;
                            nextb += KCHUNK;
                        }
                        float2 w = *(const float2*)&sm[k * JPAD + jp * 2];
                        p0 = __fadd_rn(p0, w.x);
                        p1 = __fadd_rn(p1, w.y);
                    }
                    __syncwarp();
                }
                acc0 = __fadd_rn(acc0, p0);
                acc1 = __fadd_rn(acc1, p1);

                // Epilogue: I = ff + rec; v = 0.9*v + I UNCONTRACTED.
                float I0 = __fadd_rn(ff.x, acc0);
                float I1 = __fadd_rn(ff.y, acc1);
                vx = __fadd_rn(__fmul_rn(DECAY, vx), I0);
                vy = __fadd_rn(__fmul_rn(DECAY, vy), I1);
                unsigned b0 = (vx >= VTH) ? 1u : 0u;
                unsigned b1 = (vy >= VTH) ? 1u : 0u;
                if (b0) vx = 0.0f;
                if (b1) vy = 0.0f;
                sx += (float)b0;
                sy += (float)b1;

                unsigned nib = b0 | (b1 << 1);
                atomicOr(&msk[b], nib << (jp * 2));
                __syncthreads();
                if (tid < 64) g_mask[wb][tid * NRES_BLOCKS + bid] = msk[tid];
            }
        } else {
            // Classifier on s_{t-1}: serial ascending-k mask walk (frozen).
            if (t > 0 && cidx < BB * NCLS) {
                int cb  = cidx / NCLS;
                int cls = cidx % NCLS;
                const unsigned* mrow = &g_mask[rb][cb * NRES_BLOCKS];
                const float* wr = Wclf + (size_t)cls * NRES;
                float acc = 0.f;
                for (int i = 0; i < NRES_BLOCKS; i++) {
                    unsigned m = mrow[i];
                    while (m) {
                        unsigned u = m & (0u - m);
                        int k = (i << 4) + __popc(u - 1u);
                        m ^= u;
                        acc = __fadd_rn(acc, wr[k]);
                    }
                }
                vc = __fadd_rn(__fmul_rn(DECAY, vc), acc);
                if (vc >= VTH) { cnt += 1.0f; vc = 0.0f; }
            }
        }

        __threadfence();
        grid_barrier(&sense_sm);
    }

    // Final output writes (d_out was poisoned; cover every element).
    if (bid < NRES_BLOCKS) {
        size_t off = (size_t)b * NRES + bid * 16 + jp * 2;
        float2 a; a.x = sx; a.y = sy;
        *(float2*)(d_out + NCLS * BB + off) = a;
    } else if (cidx < BB * NCLS) {
        d_out[cidx] = cnt;
    }
}

// ---------------------------------------------------------------------------
extern "C" void kernel_launch(void* const* d_in, const int* in_sizes, int n_in,
                              void* d_out, int out_size) {
    const float* x    = (const float*)d_in[0];  // (64,128,500)
    const float* Win  = (const float*)d_in[1];  // (2048,128)
    const float* Wres = (const float*)d_in[2];  // (2048,2048)
    const float* Wclf = (const float*)d_in[3];  // (10,2048)
    float* out = (float*)d_out;                 // [640 counts | 131072 accum]

    cudaFuncSetAttribute(sim_kernel,
                         cudaFuncAttributeMaxDynamicSharedMemorySize, SMEM_BYTES);

    zero_init_kernel<<<(2 * BB * NRES_BLOCKS + 255) / 256, 256>>>();
    transpose_win_kernel<<<(CC * NRES + 255) / 256, 256>>>(Win);
    build_wslice_kernel<<<dim3(NRES / 32, NRES / 32), dim3(32, 8)>>>(Wres);

    // Precompute all feedforward drives FF[t][b][j]
    ff_kernel<<<TT * BB, 256>>>(x);

    // One persistent kernel runs all 501 steps with a software grid barrier.
    sim_kernel<<<GRID_BLOCKS, THREADS, SMEM_BYTES>>>(Wclf, out);
}

// round 16
// speedup vs baseline: 2.0782x; 1.4231x over previous
#include <cuda_runtime.h>

// Problem constants
#define BB    64
#define CC    128
#define TT    500
#define NRES  2048
#define NCLS  10
#define DECAY 0.9f
#define VTH   1.0f

// Eigen gebp single-thread kc (CONFIRMED bit-exact). Do not change.
#define KCHUNK 232
#define HALF_K 1160          // = 5*KCHUNK: chunk-aligned split point

#define NRES_BLOCKS 128      // 16 neurons per reservoir block
#define CLF_BLOCKS  2
#define GRID_BLOCKS (NRES_BLOCKS + CLF_BLOCKS)   // 130 <= 148 SMs, 1 blk/SM
#define THREADS 512
#define JPAD 20              // smem row stride in floats
#define FFT 4                // ff kernel t-tiling

#define SM_W_FLOATS    (NRES * JPAD)       // 40960
#define SM_EXCH_FLOATS (64 * 4 * 4 * 4)    // 64b x 4jq x 4 slots x float4
#define SMEM_BYTES ((SM_W_FLOATS + SM_EXCH_FLOATS) * 4 + 64 * 4)

// Persistent device scratch
__device__ float    g_FF[(size_t)TT * BB * NRES];
__device__ unsigned g_mask[2][BB * NRES_BLOCKS];
__device__ unsigned short g_list[BB][NRES];   // flat ascending spike lists
__device__ int      g_cnt[BB];
__device__ int      g_split[BB];              // #spikes with k < HALF_K
__device__ float    g_WinT[CC * NRES];
__device__ float    g_Wslice[(size_t)NRES_BLOCKS * NRES * 16];
__device__ unsigned g_bar_count;
__device__ unsigned g_bar_sense;

// ---------------------------------------------------------------------------
__global__ void zero_init_kernel() {
    int i = blockIdx.x * blockDim.x + threadIdx.x;
    if (i < 2 * BB * NRES_BLOCKS) (&g_mask[0][0])[i] = 0u;
    if (i == 0) { g_bar_count = 0u; g_bar_sense = 0u; }
}

// ---------------------------------------------------------------------------
__global__ void transpose_win_kernel(const float* __restrict__ Win) {
    int i = blockIdx.x * blockDim.x + threadIdx.x;
    if (i < CC * NRES) {
        int c = i / NRES;
        int j = i % NRES;
        g_WinT[i] = Win[j * CC + c];
    }
}

// ---------------------------------------------------------------------------
__global__ void build_wslice_kernel(const float* __restrict__ Wres) {
    __shared__ float tile[32][33];
    int kBase = blockIdx.x * 32;
    int jBase = blockIdx.y * 32;
    int tx = threadIdx.x;
    int ty = threadIdx.y;
    for (int r = ty; r < 32; r += 8)
        tile[r][tx] = Wres[(size_t)(jBase + r) * NRES + kBase + tx];
    __syncthreads();
    for (int r = ty; r < 32; r += 8) {
        int k = kBase + r;
        int j = jBase + tx;
        g_Wslice[((size_t)(j >> 4) * NRES + k) * 16 + (j & 15)] = tile[tx][r];
    }
}

// ---------------------------------------------------------------------------
// FF: 4 timesteps per block. Each (t,b,j) keeps its own serial ascending-c
// fmaf chain -> bit-identical to the frozen contract.
__global__ void __launch_bounds__(256) ff_kernel(const float* __restrict__ x) {
    int tb = blockIdx.x / BB;
    int b  = blockIdx.x % BB;
    int t0 = tb * FFT;
    __shared__ float xs[FFT][CC];
    int tid = threadIdx.x;
    if (tid < CC) {
        #pragma unroll
        for (int u = 0; u < FFT; u++)
            xs[u][tid] = x[(size_t)b * CC * TT + tid * TT + t0 + u];
    }
    __syncthreads();

    const float4* W4 = (const float4*)g_WinT;
    float4 A0[FFT], A1[FFT];
    #pragma unroll
    for (int u = 0; u < FFT; u++) {
        A0[u] = make_float4(0.f, 0.f, 0.f, 0.f);
        A1[u] = make_float4(0.f, 0.f, 0.f, 0.f);
    }
    #pragma unroll 2
    for (int c = 0; c < CC; c++) {
        float4 w0 = W4[c * (NRES / 4) + tid];
        float4 w1 = W4[c * (NRES / 4) + tid + 256];
        #pragma unroll
        for (int u = 0; u < FFT; u++) {
            float xv = xs[u][c];
            A0[u].x = fmaf(xv, w0.x, A0[u].x); A0[u].y = fmaf(xv, w0.y, A0[u].y);
            A0[u].z = fmaf(xv, w0.z, A0[u].z); A0[u].w = fmaf(xv, w0.w, A0[u].w);
            A1[u].x = fmaf(xv, w1.x, A1[u].x); A1[u].y = fmaf(xv, w1.y, A1[u].y);
            A1[u].z = fmaf(xv, w1.z, A1[u].z); A1[u].w = fmaf(xv, w1.w, A1[u].w);
        }
    }
    #pragma unroll
    for (int u = 0; u < FFT; u++) {
        float4* out = (float4*)(g_FF + (size_t)(t0 + u) * BB * NRES
                                + (size_t)b * NRES);
        out[tid]       = A0[u];
        out[tid + 256] = A1[u];
    }
}

// ---------------------------------------------------------------------------
__device__ __forceinline__ void grid_barrier(unsigned* sense_sm) {
    __syncthreads();
    if (threadIdx.x == 0) {
        unsigned s = *sense_sm ^ 1u;
        *sense_sm = s;
        __threadfence();
        unsigned v = atomicAdd(&g_bar_count, 1u);
        if (v == GRID_BLOCKS - 1u) {
            atomicExch(&g_bar_count, 0u);
            __threadfence();
            atomicExch(&g_bar_sense, s);
        } else {
            volatile unsigned* vs = &g_bar_sense;
            while (*vs != s) __nanosleep(128);
        }
        __threadfence();
    }
    __syncthreads();
}

// ---------------------------------------------------------------------------
// Persistent sim: per step, PART A builds flat lists (warp0 of blocks 0..63)
// and prefetches FF; PART B consumes with (b, jq, k-half) float4 threads.
// k-half split at 1160 is a chunk boundary: half0 = chunks 0-4 combined with
// the standard flush chain; half1 keeps chunks 5-8 as SEPARATE partials,
// combined by half0 in exact ascending order -> bit-identical to reference.
__global__ void __launch_bounds__(THREADS, 1)
sim_kernel(const float* __restrict__ Wclf, float* __restrict__ d_out) {
    extern __shared__ float sm[];
    float* exch = sm + SM_W_FLOATS;
    unsigned* msk = (unsigned*)(exch + SM_EXCH_FLOATS);
    __shared__ unsigned sense_sm;
    int tid = threadIdx.x;
    int bid = blockIdx.x;
    int lane = tid & 31;
    if (tid == 0) sense_sm = 0u;

    int half = tid >> 8;          // 0: chunks 0-4, 1: chunks 5-8
    int b    = (tid >> 2) & 63;
    int jq   = tid & 3;

    float4 v    = make_float4(0.f, 0.f, 0.f, 0.f);
    float4 sacc = make_float4(0.f, 0.f, 0.f, 0.f);
    int   cidx = (bid - NRES_BLOCKS) * THREADS + tid;
    float vc = 0.f, ccnt = 0.f;

    if (bid < NRES_BLOCKS) {
        const float4* src = (const float4*)(g_Wslice + (size_t)bid * NRES * 16);
        float4* dst = (float4*)sm;
        #pragma unroll
        for (int u = 0; u < 16; u++) {
            int f = tid + u * THREADS;
            int k = f >> 2, q = f & 3;
            dst[k * (JPAD / 4) + q] = src[f];
        }
    }
    __syncthreads();

    for (int t = 0; t <= TT; t++) {
        int rb = (t + 1) & 1;
        int wb = t & 1;

        // ================= PART A =================
        float4 ff = make_float4(0.f, 0.f, 0.f, 0.f);
        if (bid < NRES_BLOCKS) {
            if (t < TT && half == 0) {
                size_t off = (size_t)b * NRES + bid * 16 + jq * 4;
                ff = *(const float4*)(g_FF + (size_t)t * BB * NRES + off);
            }
            if (bid < BB && tid < 32) {
                // Build flat ascending list for batch row `bid`.
                const unsigned* mrow = &g_mask[rb][bid * NRES_BLOCKS];
                unsigned w[4]; int c = 0;
                #pragma unroll
                for (int q = 0; q < 4; q++) {
                    w[q] = mrow[lane * 4 + q];
                    c += __popc(w[q]);
                }
                int incl = c;
                #pragma unroll
                for (int d = 1; d < 32; d <<= 1) {
                    int nn = __shfl_up_sync(0xFFFFFFFFu, incl, d);
                    if (lane >= d) incl += nn;
                }
                int pos = incl - c;
                // split = #spikes with k < 1160 (lane18 word0 bits 0-7)
                int clo = (lane < 18) ? c
                        : ((lane == 18) ? __popc(w[0] & 0xFFu) : 0);
                #pragma unroll
                for (int d = 16; d; d >>= 1)
                    clo += __shfl_down_sync(0xFFFFFFFFu, clo, d);
                unsigned short* dstl = &g_list[bid][0];
                #pragma unroll
                for (int q = 0; q < 4; q++) {
                    int kb = lane * 64 + q * 16;
                    unsigned m = w[q];
                    while (m) {
                        unsigned u2 = m & (0u - m);
                        dstl[pos++] = (unsigned short)(kb + __popc(u2 - 1u));
                        m ^= u2;
                    }
                }
                if (lane == 31) g_cnt[bid] = incl;
                if (lane == 0)  g_split[bid] = clo;
            }
        }
        __threadfence();
        grid_barrier(&sense_sm);

        // ================= PART B =================
        if (bid < NRES_BLOCKS) {
            if (t < TT) {
                if (tid < 64) msk[tid] = 0u;
                int n     = g_cnt[b];
                int split = g_split[b];
                const unsigned short* lst = &g_list[b][0];
                __syncthreads();   // S1

                float4 acc = make_float4(0.f, 0.f, 0.f, 0.f);
                float4 p   = make_float4(0.f, 0.f, 0.f, 0.f);
                float4 q0 = p, q1 = p, q2 = p, q3 = p;

                if (half == 0) {
                    int nextb = KCHUNK;
                    int i = 0;
                    for (; i + 4 <= split; i += 4) {
                        int k0 = lst[i],     k1 = lst[i + 1];
                        int k2 = lst[i + 2], k3 = lst[i + 3];
                        if (k3 < nextb) {
                            float4 wa = *(const float4*)&sm[k0 * JPAD + jq * 4];
                            float4 wbq = *(const float4*)&sm[k1 * JPAD + jq * 4];
                            float4 wc = *(const float4*)&sm[k2 * JPAD + jq * 4];
                            float4 wd = *(const float4*)&sm[k3 * JPAD + jq * 4];
                            p.x = __fadd_rn(p.x, wa.x);  p.y = __fadd_rn(p.y, wa.y);
                            p.z = __fadd_rn(p.z, wa.z);  p.w = __fadd_rn(p.w, wa.w);
                            p.x = __fadd_rn(p.x, wbq.x); p.y = __fadd_rn(p.y, wbq.y);
                            p.z = __fadd_rn(p.z, wbq.z); p.w = __fadd_rn(p.w, wbq.w);
                            p.x = __fadd_rn(p.x, wc.x);  p.y = __fadd_rn(p.y, wc.y);
                            p.z = __fadd_rn(p.z, wc.z);  p.w = __fadd_rn(p.w, wc.w);
                            p.x = __fadd_rn(p.x, wd.x);  p.y = __fadd_rn(p.y, wd.y);
                            p.z = __fadd_rn(p.z, wd.z);  p.w = __fadd_rn(p.w, wd.w);
                        } else {
                            #pragma unroll
                            for (int q = 0; q < 4; q++) {
                                int k = lst[i + q];
                                while (k >= nextb) {
                                    acc.x = __fadd_rn(acc.x, p.x);
                                    acc.y = __fadd_rn(acc.y, p.y);
                                    acc.z = __fadd_rn(acc.z, p.z);
                                    acc.w = __fadd_rn(acc.w, p.w);
                                    p = make_float4(0.f, 0.f, 0.f, 0.f);
                                    nextb += KCHUNK;
                                }
                                float4 wq = *(const float4*)&sm[k * JPAD + jq * 4];
                                p.x = __fadd_rn(p.x, wq.x); p.y = __fadd_rn(p.y, wq.y);
                                p.z = __fadd_rn(p.z, wq.z); p.w = __fadd_rn(p.w, wq.w);
                            }
                        }
                    }
                    for (; i < split; i++) {
                        int k = lst[i];
                        while (k >= nextb) {
                            acc.x = __fadd_rn(acc.x, p.x);
                            acc.y = __fadd_rn(acc.y, p.y);
                            acc.z = __fadd_rn(acc.z, p.z);
                            acc.w = __fadd_rn(acc.w, p.w);
                            p = make_float4(0.f, 0.f, 0.f, 0.f);
                            nextb += KCHUNK;
                        }
                        float4 wq = *(const float4*)&sm[k * JPAD + jq * 4];
                        p.x = __fadd_rn(p.x, wq.x); p.y = __fadd_rn(p.y, wq.y);
                        p.z = __fadd_rn(p.z, wq.z); p.w = __fadd_rn(p.w, wq.w);
                    }
                    acc.x = __fadd_rn(acc.x, p.x);
                    acc.y = __fadd_rn(acc.y, p.y);
                    acc.z = __fadd_rn(acc.z, p.z);
                    acc.w = __fadd_rn(acc.w, p.w);
                } else {
                    int slot = 0, nextq = HALF_K + KCHUNK;   // 1392
                    int i = split;
                    for (; i + 4 <= n; i += 4) {
                        int k0 = lst[i],     k1 = lst[i + 1];
                        int k2 = lst[i + 2], k3 = lst[i + 3];
                        if (k3 < nextq) {
                            float4 wa = *(const float4*)&sm[k0 * JPAD + jq * 4];
                            float4 wbq = *(const float4*)&sm[k1 * JPAD + jq * 4];
                            float4 wc = *(const float4*)&sm[k2 * JPAD + jq * 4];
                            float4 wd = *(const float4*)&sm[k3 * JPAD + jq * 4];
                            p.x = __fadd_rn(p.x, wa.x);  p.y = __fadd_rn(p.y, wa.y);
                            p.z = __fadd_rn(p.z, wa.z);  p.w = __fadd_rn(p.w, wa.w);
                            p.x = __fadd_rn(p.x, wbq.x); p.y = __fadd_rn(p.y, wbq.y);
                            p.z = __fadd_rn(p.z, wbq.z); p.w = __fadd_rn(p.w, wbq.w);
                            p.x = __fadd_rn(p.x, wc.x);  p.y = __fadd_rn(p.y, wc.y);
                            p.z = __fadd_rn(p.z, wc.z);  p.w = __fadd_rn(p.w, wc.w);
                            p.x = __fadd_rn(p.x, wd.x);  p.y = __fadd_rn(p.y, wd.y);
                            p.z = __fadd_rn(p.z, wd.z);  p.w = __fadd_rn(p.w, wd.w);
                        } else {
                            #pragma unroll
                            for (int q = 0; q < 4; q++) {
                                int k = lst[i + q];
                                while (k >= nextq) {
                                    if (slot == 0) q0 = p;
                                    else if (slot == 1) q1 = p;
                                    else q2 = p;
                                    p = make_float4(0.f, 0.f, 0.f, 0.f);
                                    slot++; nextq += KCHUNK;
                                }
                                float4 wq = *(const float4*)&sm[k * JPAD + jq * 4];
                                p.x = __fadd_rn(p.x, wq.x); p.y = __fadd_rn(p.y, wq.y);
                                p.z = __fadd_rn(p.z, wq.z); p.w = __fadd_rn(p.w, wq.w);
                            }
                        }
                    }
                    for (; i < n; i++) {
                        int k = lst[i];
                        while (k >= nextq) {
                            if (slot == 0) q0 = p;
                            else if (slot == 1) q1 = p;
                            else q2 = p;
                            p = make_float4(0.f, 0.f, 0.f, 0.f);
                            slot++; nextq += KCHUNK;
                        }
                        float4 wq = *(const float4*)&sm[k * JPAD + jq * 4];
                        p.x = __fadd_rn(p.x, wq.x); p.y = __fadd_rn(p.y, wq.y);
                        p.z = __fadd_rn(p.z, wq.z); p.w = __fadd_rn(p.w, wq.w);
                    }
                    if (slot == 0) q0 = p;
                    else if (slot == 1) q1 = p;
                    else if (slot == 2) q2 = p;
                    else q3 = p;
                    float4* ex = (float4*)exch + ((b * 4 + jq) * 4);
                    ex[0] = q0; ex[1] = q1; ex[2] = q2; ex[3] = q3;
                }
                __syncthreads();   // S2: exch published

                if (half == 0) {
                    float4* ex = (float4*)exch + ((b * 4 + jq) * 4);
                    float4 e0 = ex[0], e1 = ex[1], e2 = ex[2], e3 = ex[3];
                    // ordered combine: chunks 5,6,7,8
                    acc.x = __fadd_rn(acc.x, e0.x); acc.y = __fadd_rn(acc.y, e0.y);
                    acc.z = __fadd_rn(acc.z, e0.z); acc.w = __fadd_rn(acc.w, e0.w);
                    acc.x = __fadd_rn(acc.x, e1.x); acc.y = __fadd_rn(acc.y, e1.y);
                    acc.z = __fadd_rn(acc.z, e1.z); acc.w = __fadd_rn(acc.w, e1.w);
                    acc.x = __fadd_rn(acc.x, e2.x); acc.y = __fadd_rn(acc.y, e2.y);
                    acc.z = __fadd_rn(acc.z, e2.z); acc.w = __fadd_rn(acc.w, e2.w);
                    acc.x = __fadd_rn(acc.x, e3.x); acc.y = __fadd_rn(acc.y, e3.y);
                    acc.z = __fadd_rn(acc.z, e3.z); acc.w = __fadd_rn(acc.w, e3.w);

                    float4 I;
                    I.x = __fadd_rn(ff.x, acc.x);
                    I.y = __fadd_rn(ff.y, acc.y);
                    I.z = __fadd_rn(ff.z, acc.z);
                    I.w = __fadd_rn(ff.w, acc.w);
                    v.x = __fadd_rn(__fmul_rn(DECAY, v.x), I.x);
                    v.y = __fadd_rn(__fmul_rn(DECAY, v.y), I.y);
                    v.z = __fadd_rn(__fmul_rn(DECAY, v.z), I.z);
                    v.w = __fadd_rn(__fmul_rn(DECAY, v.w), I.w);
                    unsigned b0 = (v.x >= VTH) ? 1u : 0u;
                    unsigned b1 = (v.y >= VTH) ? 1u : 0u;
                    unsigned b2 = (v.z >= VTH) ? 1u : 0u;
                    unsigned b3 = (v.w >= VTH) ? 1u : 0u;
                    if (b0) v.x = 0.0f;
                    if (b1) v.y = 0.0f;
                    if (b2) v.z = 0.0f;
                    if (b3) v.w = 0.0f;
                    sacc.x += (float)b0; sacc.y += (float)b1;
                    sacc.z += (float)b2; sacc.w += (float)b3;
                    unsigned nib = b0 | (b1 << 1) | (b2 << 2) | (b3 << 3);
                    atomicOr(&msk[b], nib << (jq * 4));
                }
                __syncthreads();   // S3
                if (tid < 64) g_mask[wb][tid * NRES_BLOCKS + bid] = msk[tid];
            }
        } else {
            // Classifier on s_{t-1}: serial ascending-k adds over flat list.
            if (t >= 1 && cidx < BB * NCLS) {
                int cb  = cidx / NCLS;
                int cls = cidx % NCLS;
                int n = g_cnt[cb];
                const unsigned short* lst = &g_list[cb][0];
                const float* wr = Wclf + (size_t)cls * NRES;
                float acc = 0.f;
                int i = 0;
                for (; i + 4 <= n; i += 4) {
                    float l0 = wr[lst[i]],     l1 = wr[lst[i + 1]];
                    float l2 = wr[lst[i + 2]], l3 = wr[lst[i + 3]];
                    acc = __fadd_rn(acc, l0);
                    acc = __fadd_rn(acc, l1);
                    acc = __fadd_rn(acc, l2);
                    acc = __fadd_rn(acc, l3);
                }
                for (; i < n; i++) acc = __fadd_rn(acc, wr[lst[i]]);
                vc = __fadd_rn(__fmul_rn(DECAY, vc), acc);
                if (vc >= VTH) { ccnt += 1.0f; vc = 0.0f; }
            }
        }
        __threadfence();
        grid_barrier(&sense_sm);
    }

    // Final output writes (d_out poisoned; cover every element).
    if (bid < NRES_BLOCKS) {
        if (half == 0) {
            size_t off = (size_t)b * NRES + bid * 16 + jq * 4;
            *(float4*)(d_out + NCLS * BB + off) = sacc;
        }
    } else if (cidx < BB * NCLS) {
        d_out[cidx] = ccnt;
    }
}

// ---------------------------------------------------------------------------
extern "C" void kernel_launch(void* const* d_in, const int* in_sizes, int n_in,
                              void* d_out, int out_size) {
    const float* x    = (const float*)d_in[0];  // (64,128,500)
    const float* Win  = (const float*)d_in[1];  // (2048,128)
    const float* Wres = (const float*)d_in[2];  // (2048,2048)
    const float* Wclf = (const float*)d_in[3];  // (10,2048)
    float* out = (float*)d_out;                 // [640 counts | 131072 accum]

    cudaFuncSetAttribute(sim_kernel,
                         cudaFuncAttributeMaxDynamicSharedMemorySize, SMEM_BYTES);

    zero_init_kernel<<<(2 * BB * NRES_BLOCKS + 255) / 256, 256>>>();
    transpose_win_kernel<<<(CC * NRES + 255) / 256, 256>>>(Win);
    build_wslice_kernel<<<dim3(NRES / 32, NRES / 32), dim3(32, 8)>>>(Wres);

    // Precompute all feedforward drives (4 timesteps per block).
    ff_kernel<<<(TT / FFT) * BB, 256>>>(x);

    // One persistent kernel runs all 501 steps, 2 grid barriers each.
    sim_kernel<<<GRID_BLOCKS, THREADS, SMEM_BYTES>>>(Wclf, out);
}

// round 17
// speedup vs baseline: 3.5280x; 1.6976x over previous
#include <cuda_runtime.h>

// Problem constants
#define BB    64
#define CC    128
#define TT    500
#define NRES  2048
#define NCLS  10
#define DECAY 0.9f
#define VTH   1.0f

// Eigen gebp single-thread kc (CONFIRMED bit-exact). Do not change.
#define KCHUNK 232
#define HALF_K 1160          // = 5*KCHUNK: chunk-aligned split point

#define NRES_BLOCKS 128      // 16 neurons per reservoir block; grid = 128
#define THREADS 512
#define JPAD 20              // smem row stride in floats
#define FFT 4                // ff kernel t-tiling

#define SM_W_FLOATS    (NRES * JPAD)       // 40960
#define SM_EXCH_FLOATS (64 * 4 * 4 * 4)    // 64b x 4jq x 4 slots x float4
#define SMEM_BYTES ((SM_W_FLOATS + SM_EXCH_FLOATS) * 4 + 64 * 4)

// Persistent device scratch
__device__ float    g_FF[(size_t)TT * BB * NRES];
__device__ unsigned g_mask[2][BB * NRES_BLOCKS];
__device__ unsigned short g_list[2][BB][NRES];  // double-buffered flat lists
__device__ int      g_cnt[2][BB];
__device__ int      g_split[2][BB];             // #spikes with k < HALF_K
__device__ float    g_WinT[CC * NRES];
__device__ float    g_Wslice[(size_t)NRES_BLOCKS * NRES * 16];
__device__ unsigned g_arrive;   // monotonic: +128 per produced step
__device__ unsigned g_build;    // monotonic: +64 per built list set

// ---------------------------------------------------------------------------
__device__ __forceinline__ unsigned ld_acq(const unsigned* p) {
    unsigned v;
    asm volatile("ld.acquire.gpu.u32 %0, [%1];" : "=r"(v) : "l"(p) : "memory");
    return v;
}
__device__ __forceinline__ void red_rel_add1(unsigned* p) {
    asm volatile("red.release.gpu.add.u32 [%0], 1;" :: "l"(p) : "memory");
}
__device__ __forceinline__ void spin_ge(const unsigned* p, unsigned tgt) {
    while (ld_acq(p) < tgt) { }
}

// ---------------------------------------------------------------------------
__global__ void zero_init_kernel() {
    int i = blockIdx.x * blockDim.x + threadIdx.x;
    if (i < 2 * BB * NRES_BLOCKS) (&g_mask[0][0])[i] = 0u;
    if (i < 2 * BB)               (&g_cnt[0][0])[i] = 0;
    if (i < 2 * BB)               (&g_split[0][0])[i] = 0;
    if (i == 0) { g_arrive = 0u; g_build = 0u; }
}

// ---------------------------------------------------------------------------
__global__ void transpose_win_kernel(const float* __restrict__ Win) {
    int i = blockIdx.x * blockDim.x + threadIdx.x;
    if (i < CC * NRES) {
        int c = i / NRES;
        int j = i % NRES;
        g_WinT[i] = Win[j * CC + c];
    }
}

// ---------------------------------------------------------------------------
__global__ void build_wslice_kernel(const float* __restrict__ Wres) {
    __shared__ float tile[32][33];
    int kBase = blockIdx.x * 32;
    int jBase = blockIdx.y * 32;
    int tx = threadIdx.x;
    int ty = threadIdx.y;
    for (int r = ty; r < 32; r += 8)
        tile[r][tx] = Wres[(size_t)(jBase + r) * NRES + kBase + tx];
    __syncthreads();
    for (int r = ty; r < 32; r += 8) {
        int k = kBase + r;
        int j = jBase + tx;
        g_Wslice[((size_t)(j >> 4) * NRES + k) * 16 + (j & 15)] = tile[tx][r];
    }
}

// ---------------------------------------------------------------------------
// FF: 4 timesteps per block; serial ascending-c fmaf chain per output (frozen).
__global__ void __launch_bounds__(256) ff_kernel(const float* __restrict__ x) {
    int tb = blockIdx.x / BB;
    int b  = blockIdx.x % BB;
    int t0 = tb * FFT;
    __shared__ float xs[FFT][CC];
    int tid = threadIdx.x;
    if (tid < CC) {
        #pragma unroll
        for (int u = 0; u < FFT; u++)
            xs[u][tid] = x[(size_t)b * CC * TT + tid * TT + t0 + u];
    }
    __syncthreads();

    const float4* W4 = (const float4*)g_WinT;
    float4 A0[FFT], A1[FFT];
    #pragma unroll
    for (int u = 0; u < FFT; u++) {
        A0[u] = make_float4(0.f, 0.f, 0.f, 0.f);
        A1[u] = make_float4(0.f, 0.f, 0.f, 0.f);
    }
    #pragma unroll 2
    for (int c = 0; c < CC; c++) {
        float4 w0 = W4[c * (NRES / 4) + tid];
        float4 w1 = W4[c * (NRES / 4) + tid + 256];
        #pragma unroll
        for (int u = 0; u < FFT; u++) {
            float xv = xs[u][c];
            A0[u].x = fmaf(xv, w0.x, A0[u].x); A0[u].y = fmaf(xv, w0.y, A0[u].y);
            A0[u].z = fmaf(xv, w0.z, A0[u].z); A0[u].w = fmaf(xv, w0.w, A0[u].w);
            A1[u].x = fmaf(xv, w1.x, A1[u].x); A1[u].y = fmaf(xv, w1.y, A1[u].y);
            A1[u].z = fmaf(xv, w1.z, A1[u].z); A1[u].w = fmaf(xv, w1.w, A1[u].w);
        }
    }
    #pragma unroll
    for (int u = 0; u < FFT; u++) {
        float4* out = (float4*)(g_FF + (size_t)(t0 + u) * BB * NRES
                                + (size_t)b * NRES);
        out[tid]       = A0[u];
        out[tid + 256] = A1[u];
    }
}

// ---------------------------------------------------------------------------
// Persistent sim with flow-counter pipeline (no full grid barriers):
//   producers arrive on g_arrive (+128/step) -> builders (blocks 0-63 warp0)
//   build flat lists, arrive on g_build (+64/step) -> consumers gate on it.
// Classifier = blocks 64-127 warp0, consumes the PREVIOUS iteration's list
// (double-buffered) so it is off the critical path.
// Numerics frozen: ascending-k, 232-boundary flushes, uncontracted epilogue.
__global__ void __launch_bounds__(THREADS, 1)
sim_kernel(const float* __restrict__ Wclf, float* __restrict__ d_out) {
    extern __shared__ float sm[];
    float* exch = sm + SM_W_FLOATS;
    unsigned* msk = (unsigned*)(exch + SM_EXCH_FLOATS);
    int tid  = threadIdx.x;
    int bid  = blockIdx.x;
    int lane = tid & 31;
    int wid  = tid >> 5;

    int half = tid >> 8;          // 0: chunks 0-4, 1: chunks 5-8
    int b    = (tid >> 2) & 63;
    int jq   = tid & 3;

    float4 v    = make_float4(0.f, 0.f, 0.f, 0.f);
    float4 sacc = make_float4(0.f, 0.f, 0.f, 0.f);
    float vc = 0.f, ccnt = 0.f;
    int clf_b = bid - 64;         // valid for classifier blocks

    // Stage W slice once.
    {
        const float4* src = (const float4*)(g_Wslice + (size_t)bid * NRES * 16);
        float4* dst = (float4*)sm;
        #pragma unroll
        for (int u = 0; u < 16; u++) {
            int f = tid + u * THREADS;
            int k = f >> 2, q = f & 3;
            dst[k * (JPAD / 4) + q] = src[f];
        }
    }
    __syncthreads();

    for (int t = 0; t <= TT + 1; t++) {
        int lb = t & 1;   // list buffer consumed/built this iteration

        // FF prefetch (long latency; independent of gates).
        float4 ff = make_float4(0.f, 0.f, 0.f, 0.f);
        if (t < TT && half == 0) {
            size_t off = (size_t)b * NRES + bid * 16 + jq * 4;
            ff = *(const float4*)(g_FF + (size_t)t * BB * NRES + off);
        }

        // ---- Builders: blocks 0-63 warp0, 1 <= t <= TT ----
        if (bid < BB && wid == 0 && t >= 1 && t <= TT) {
            if (lane == 0) spin_ge(&g_arrive, 128u * (unsigned)t);
            __syncwarp();
            const unsigned* mrow = &g_mask[(t - 1) & 1][bid * NRES_BLOCKS];
            unsigned w[4]; int c = 0;
            #pragma unroll
            for (int q = 0; q < 4; q++) {
                w[q] = mrow[lane * 4 + q];
                c += __popc(w[q]);
            }
            int incl = c;
            #pragma unroll
            for (int d = 1; d < 32; d <<= 1) {
                int nn = __shfl_up_sync(0xFFFFFFFFu, incl, d);
                if (lane >= d) incl += nn;
            }
            int pos = incl - c;
            // split = #spikes with k < 1160 (word 72 bits 0-7)
            int clo = (lane < 18) ? c
                    : ((lane == 18) ? __popc(w[0] & 0xFFu) : 0);
            #pragma unroll
            for (int d = 16; d; d >>= 1)
                clo += __shfl_down_sync(0xFFFFFFFFu, clo, d);
            unsigned short* dstl = &g_list[lb][bid][0];
            #pragma unroll
            for (int q = 0; q < 4; q++) {
                int kb = lane * 64 + q * 16;
                unsigned m = w[q];
                while (m) {
                    unsigned u2 = m & (0u - m);
                    dstl[pos++] = (unsigned short)(kb + __popc(u2 - 1u));
                    m ^= u2;
                }
            }
            if (lane == 31) g_cnt[lb][bid] = incl;
            if (lane == 0)  g_split[lb][bid] = clo;
            __syncwarp();
            if (lane == 0) red_rel_add1(&g_build);
        }

        // ---- Classifier: blocks 64-127 warp0, 2 <= t <= TT+1, s_{t-2} ----
        if (bid >= BB && wid == 0 && t >= 2) {
            if (lane == 0) spin_ge(&g_build, 64u * (unsigned)(t - 1));
            __syncwarp();
            if (lane < NCLS) {
                int pb = (t - 1) & 1;
                int n = g_cnt[pb][clf_b];
                const unsigned short* lst = &g_list[pb][clf_b][0];
                const float* wr = Wclf + (size_t)lane * NRES;
                float acc = 0.f;
                int i = 0;
                for (; i + 4 <= n; i += 4) {
                    uint2 q = *(const uint2*)(lst + i);
                    float l0 = wr[q.x & 0xFFFFu], l1 = wr[q.x >> 16];
                    float l2 = wr[q.y & 0xFFFFu], l3 = wr[q.y >> 16];
                    acc = __fadd_rn(acc, l0);
                    acc = __fadd_rn(acc, l1);
                    acc = __fadd_rn(acc, l2);
                    acc = __fadd_rn(acc, l3);
                }
                for (; i < n; i++) acc = __fadd_rn(acc, wr[lst[i]]);
                vc = __fadd_rn(__fmul_rn(DECAY, vc), acc);
                if (vc >= VTH) { ccnt += 1.0f; vc = 0.0f; }
            }
        }

        // ---- Consume + produce: all blocks, t < TT ----
        if (t < TT) {
            if (tid == 0) spin_ge(&g_build, 64u * (unsigned)t);
            if (tid < 64) msk[tid] = 0u;
            __syncthreads();   // S1: gate + msk zero

            int n     = g_cnt[lb][b];
            int split = g_split[lb][b];
            const unsigned short* lst = &g_list[lb][b][0];

            float4 acc = make_float4(0.f, 0.f, 0.f, 0.f);
            float4 p   = make_float4(0.f, 0.f, 0.f, 0.f);
            float4 q0 = p, q1 = p, q2 = p, q3 = p;

            if (half == 0) {
                int nextb = KCHUNK;
                int i = 0;
                for (; i + 4 <= split; i += 4) {
                    uint2 qw = *(const uint2*)(lst + i);
                    int k0 = qw.x & 0xFFFFu, k1 = qw.x >> 16;
                    int k2 = qw.y & 0xFFFFu, k3 = qw.y >> 16;
                    if (k3 < nextb) {
                        float4 wa = *(const float4*)&sm[k0 * JPAD + jq * 4];
                        float4 wbq = *(const float4*)&sm[k1 * JPAD + jq * 4];
                        float4 wc = *(const float4*)&sm[k2 * JPAD + jq * 4];
                        float4 wd = *(const float4*)&sm[k3 * JPAD + jq * 4];
                        p.x = __fadd_rn(p.x, wa.x);  p.y = __fadd_rn(p.y, wa.y);
                        p.z = __fadd_rn(p.z, wa.z);  p.w = __fadd_rn(p.w, wa.w);
                        p.x = __fadd_rn(p.x, wbq.x); p.y = __fadd_rn(p.y, wbq.y);
                        p.z = __fadd_rn(p.z, wbq.z); p.w = __fadd_rn(p.w, wbq.w);
                        p.x = __fadd_rn(p.x, wc.x);  p.y = __fadd_rn(p.y, wc.y);
                        p.z = __fadd_rn(p.z, wc.z);  p.w = __fadd_rn(p.w, wc.w);
                        p.x = __fadd_rn(p.x, wd.x);  p.y = __fadd_rn(p.y, wd.y);
                        p.z = __fadd_rn(p.z, wd.z);  p.w = __fadd_rn(p.w, wd.w);
                    } else {
                        int kk[4] = {k0, k1, k2, k3};
                        #pragma unroll
                        for (int q = 0; q < 4; q++) {
                            int k = kk[q];
                            while (k >= nextb) {
                                acc.x = __fadd_rn(acc.x, p.x);
                                acc.y = __fadd_rn(acc.y, p.y);
                                acc.z = __fadd_rn(acc.z, p.z);
                                acc.w = __fadd_rn(acc.w, p.w);
                                p = make_float4(0.f, 0.f, 0.f, 0.f);
                                nextb += KCHUNK;
                            }
                            float4 wq = *(const float4*)&sm[k * JPAD + jq * 4];
                            p.x = __fadd_rn(p.x, wq.x); p.y = __fadd_rn(p.y, wq.y);
                            p.z = __fadd_rn(p.z, wq.z); p.w = __fadd_rn(p.w, wq.w);
                        }
                    }
                }
                for (; i < split; i++) {
                    int k = lst[i];
                    while (k >= nextb) {
                        acc.x = __fadd_rn(acc.x, p.x);
                        acc.y = __fadd_rn(acc.y, p.y);
                        acc.z = __fadd_rn(acc.z, p.z);
                        acc.w = __fadd_rn(acc.w, p.w);
                        p = make_float4(0.f, 0.f, 0.f, 0.f);
                        nextb += KCHUNK;
                    }
                    float4 wq = *(const float4*)&sm[k * JPAD + jq * 4];
                    p.x = __fadd_rn(p.x, wq.x); p.y = __fadd_rn(p.y, wq.y);
                    p.z = __fadd_rn(p.z, wq.z); p.w = __fadd_rn(p.w, wq.w);
                }
                acc.x = __fadd_rn(acc.x, p.x);
                acc.y = __fadd_rn(acc.y, p.y);
                acc.z = __fadd_rn(acc.z, p.z);
                acc.w = __fadd_rn(acc.w, p.w);
            } else {
                int slot = 0, nextq = HALF_K + KCHUNK;   // 1392
                int i = split;
                int head = (split + 3) & ~3;
                if (head > n) head = n;
                // helper lambda-like macro via plain code: singles
                for (; i < head; i++) {
                    int k = lst[i];
                    while (k >= nextq) {
                        if (slot == 0) q0 = p;
                        else if (slot == 1) q1 = p;
                        else q2 = p;
                        p = make_float4(0.f, 0.f, 0.f, 0.f);
                        slot++; nextq += KCHUNK;
                    }
                    float4 wq = *(const float4*)&sm[k * JPAD + jq * 4];
                    p.x = __fadd_rn(p.x, wq.x); p.y = __fadd_rn(p.y, wq.y);
                    p.z = __fadd_rn(p.z, wq.z); p.w = __fadd_rn(p.w, wq.w);
                }
                for (; i + 4 <= n; i += 4) {
                    uint2 qw = *(const uint2*)(lst + i);
                    int k0 = qw.x & 0xFFFFu, k1 = qw.x >> 16;
                    int k2 = qw.y & 0xFFFFu, k3 = qw.y >> 16;
                    if (k3 < nextq) {
                        float4 wa = *(const float4*)&sm[k0 * JPAD + jq * 4];
                        float4 wbq = *(const float4*)&sm[k1 * JPAD + jq * 4];
                        float4 wc = *(const float4*)&sm[k2 * JPAD + jq * 4];
                        float4 wd = *(const float4*)&sm[k3 * JPAD + jq * 4];
                        p.x = __fadd_rn(p.x, wa.x);  p.y = __fadd_rn(p.y, wa.y);
                        p.z = __fadd_rn(p.z, wa.z);  p.w = __fadd_rn(p.w, wa.w);
                        p.x = __fadd_rn(p.x, wbq.x); p.y = __fadd_rn(p.y, wbq.y);
                        p.z = __fadd_rn(p.z, wbq.z); p.w = __fadd_rn(p.w, wbq.w);
                        p.x = __fadd_rn(p.x, wc.x);  p.y = __fadd_rn(p.y, wc.y);
                        p.z = __fadd_rn(p.z, wc.z);  p.w = __fadd_rn(p.w, wc.w);
                        p.x = __fadd_rn(p.x, wd.x);  p.y = __fadd_rn(p.y, wd.y);
                        p.z = __fadd_rn(p.z, wd.z);  p.w = __fadd_rn(p.w, wd.w);
                    } else {
                        int kk[4] = {k0, k1, k2, k3};
                        #pragma unroll
                        for (int q = 0; q < 4; q++) {
                            int k = kk[q];
                            while (k >= nextq) {
                                if (slot == 0) q0 = p;
                                else if (slot == 1) q1 = p;
                                else q2 = p;
                                p = make_float4(0.f, 0.f, 0.f, 0.f);
                                slot++; nextq += KCHUNK;
                            }
                            float4 wq = *(const float4*)&sm[k * JPAD + jq * 4];
                            p.x = __fadd_rn(p.x, wq.x); p.y = __fadd_rn(p.y, wq.y);
                            p.z = __fadd_rn(p.z, wq.z); p.w = __fadd_rn(p.w, wq.w);
                        }
                    }
                }
                for (; i < n; i++) {
                    int k = lst[i];
                    while (k >= nextq) {
                        if (slot == 0) q0 = p;
                        else if (slot == 1) q1 = p;
                        else q2 = p;
                        p = make_float4(0.f, 0.f, 0.f, 0.f);
                        slot++; nextq += KCHUNK;
                    }
                    float4 wq = *(const float4*)&sm[k * JPAD + jq * 4];
                    p.x = __fadd_rn(p.x, wq.x); p.y = __fadd_rn(p.y, wq.y);
                    p.z = __fadd_rn(p.z, wq.z); p.w = __fadd_rn(p.w, wq.w);
                }
                if (slot == 0) q0 = p;
                else if (slot == 1) q1 = p;
                else if (slot == 2) q2 = p;
                else q3 = p;
                float4* ex = (float4*)exch + ((b * 4 + jq) * 4);
                ex[0] = q0; ex[1] = q1; ex[2] = q2; ex[3] = q3;
            }
            __syncthreads();   // S2: exch published

            if (half == 0) {
                float4* ex = (float4*)exch + ((b * 4 + jq) * 4);
                float4 e0 = ex[0], e1 = ex[1], e2 = ex[2], e3 = ex[3];
                acc.x = __fadd_rn(acc.x, e0.x); acc.y = __fadd_rn(acc.y, e0.y);
                acc.z = __fadd_rn(acc.z, e0.z); acc.w = __fadd_rn(acc.w, e0.w);
                acc.x = __fadd_rn(acc.x, e1.x); acc.y = __fadd_rn(acc.y, e1.y);
                acc.z = __fadd_rn(acc.z, e1.z); acc.w = __fadd_rn(acc.w, e1.w);
                acc.x = __fadd_rn(acc.x, e2.x); acc.y = __fadd_rn(acc.y, e2.y);
                acc.z = __fadd_rn(acc.z, e2.z); acc.w = __fadd_rn(acc.w, e2.w);
                acc.x = __fadd_rn(acc.x, e3.x); acc.y = __fadd_rn(acc.y, e3.y);
                acc.z = __fadd_rn(acc.z, e3.z); acc.w = __fadd_rn(acc.w, e3.w);

                float4 I;
                I.x = __fadd_rn(ff.x, acc.x);
                I.y = __fadd_rn(ff.y, acc.y);
                I.z = __fadd_rn(ff.z, acc.z);
                I.w = __fadd_rn(ff.w, acc.w);
                v.x = __fadd_rn(__fmul_rn(DECAY, v.x), I.x);
                v.y = __fadd_rn(__fmul_rn(DECAY, v.y), I.y);
                v.z = __fadd_rn(__fmul_rn(DECAY, v.z), I.z);
                v.w = __fadd_rn(__fmul_rn(DECAY, v.w), I.w);
                unsigned b0 = (v.x >= VTH) ? 1u : 0u;
                unsigned b1 = (v.y >= VTH) ? 1u : 0u;
                unsigned b2 = (v.z >= VTH) ? 1u : 0u;
                unsigned b3 = (v.w >= VTH) ? 1u : 0u;
                if (b0) v.x = 0.0f;
                if (b1) v.y = 0.0f;
                if (b2) v.z = 0.0f;
                if (b3) v.w = 0.0f;
                sacc.x += (float)b0; sacc.y += (float)b1;
                sacc.z += (float)b2; sacc.w += (float)b3;
                unsigned nib = b0 | (b1 << 1) | (b2 << 2) | (b3 << 3);
                atomicOr(&msk[b], nib << (jq * 4));
            }
            __syncthreads();   // S3: msk complete
            if (tid < 64) g_mask[t & 1][tid * NRES_BLOCKS + bid] = msk[tid];
            __syncthreads();   // S4: g_mask stores done before release
            if (tid == 0) red_rel_add1(&g_arrive);
        }
    }

    // Final output writes (cover all of d_out).
    if (half == 0) {
        size_t off = (size_t)b * NRES + bid * 16 + jq * 4;
        *(float4*)(d_out + NCLS * BB + off) = sacc;
    }
    if (bid >= BB && wid == 0 && lane < NCLS) {
        d_out[clf_b * NCLS + lane] = ccnt;
    }
}

// ---------------------------------------------------------------------------
extern "C" void kernel_launch(void* const* d_in, const int* in_sizes, int n_in,
                              void* d_out, int out_size) {
    const float* x    = (const float*)d_in[0];  // (64,128,500)
    const float* Win  = (const float*)d_in[1];  // (2048,128)
    const float* Wres = (const float*)d_in[2];  // (2048,2048)
    const float* Wclf = (const float*)d_in[3];  // (10,2048)
    float* out = (float*)d_out;                 // [640 counts | 131072 accum]

    cudaFuncSetAttribute(sim_kernel,
                         cudaFuncAttributeMaxDynamicSharedMemorySize, SMEM_BYTES);

    zero_init_kernel<<<(2 * BB * NRES_BLOCKS + 255) / 256, 256>>>();
    transpose_win_kernel<<<(CC * NRES + 255) / 256, 256>>>(Win);
    build_wslice_kernel<<<dim3(NRES / 32, NRES / 32), dim3(32, 8)>>>(Wres);

    // Precompute all feedforward drives (4 timesteps per block).
    ff_kernel<<<(TT / FFT) * BB, 256>>>(x);

    // One persistent kernel; flow counters instead of grid barriers.
    sim_kernel<<<NRES_BLOCKS, THREADS, SMEM_BYTES>>>(Wclf, out);
}